// round 12
// baseline (speedup 1.0000x reference)
#include <cuda_runtime.h>
#include <math.h>

// Problem dims
#define BB 512
#define LL 48
#define GG 16
#define HH 512
#define ZN 2048   // 4*H
#define PIN 26
#define GIN 16
#define GP 20     // padded smem row stride for 16-wide k tiles

// Persistent-kernel tiling: block = 256 batch x 16 h-cols x 4 gates, 512 threads
#define PTHREADS 512
#define PBM 256
#define PBN 16
#define WSTRIDE 516                      // 512 + 4 padding
#define WSM_WORDS (64 * WSTRIDE)         // 33024
#define APAIR_WORDS (2 * 32 * GP)        // 1280 words: 2 buffers x 32 rows x GP
#define PERSIST_SMEM ((WSM_WORDS + 8 * APAIR_WORDS) * 4)   // 173,056 bytes

// ---------------- device scratch (static, no allocs) ----------------
__device__ float g_xz[(size_t)LL * BB * 2 * ZN];          // [t][b][dir][2048]
__device__ float g_xzg[(size_t)GG * BB * ZN];             // [t][b][2048]
__device__ float g_pep_concat[(size_t)LL * BB * 2 * HH];  // [t][b][1024]
__device__ float g_gly1[(size_t)GG * BB * HH];            // [t][b][512]
__device__ float g_glymod[(size_t)BB * HH];
__device__ float g_rootpep[(size_t)BB * 2 * HH];
__device__ float g_c[2 * (size_t)BB * HH];
__device__ float g_cg[(size_t)BB * HH];
__device__ float g_pack[(size_t)(GG * BB) * (GIN + HH)];
__device__ unsigned g_bars[4 * 32];   // 4 group counters, 128B apart

__device__ __forceinline__ float* buf_ptr(int sel, float* dout) {
    switch (sel) {
        case 0: return g_pack;
        case 1: return g_xz;
        case 2: return g_xzg;
        case 3: return g_pep_concat;
        case 4: return g_gly1;
        case 5: return g_glymod;
        case 6: return g_rootpep;
        default: return dout;
    }
}

__device__ __forceinline__ unsigned f2tf(float f) {
    unsigned u; asm("cvt.rna.tf32.f32 %0, %1;" : "=r"(u) : "f"(f)); return u;
}

__device__ __forceinline__ void mma8(float* d, unsigned a0, unsigned a1, unsigned a2, unsigned a3,
                                     unsigned b0, unsigned b1) {
    asm volatile(
        "mma.sync.aligned.m16n8k8.row.col.f32.tf32.tf32.f32 "
        "{%0,%1,%2,%3}, {%4,%5,%6,%7}, {%8,%9}, {%0,%1,%2,%3};"
        : "+f"(d[0]), "+f"(d[1]), "+f"(d[2]), "+f"(d[3])
        : "r"(a0), "r"(a1), "r"(a2), "r"(a3), "r"(b0), "r"(b1));
}

__global__ void reset_bar_kernel() {
    if (threadIdx.x < 4 * 32) g_bars[threadIdx.x] = 0;
}

// ---------------- tf32 tensor-core GEMM (double-buffered) — R6/R8 proven version ----------------
// C[m][n] = bias[n] + (Cadd?) + sum_k X[m*K+k] * W[n*K+k]
// BM=128, BN=128, BK=16, 256 threads (8 warps, 4x2), warp tile 32x64.
__global__ __launch_bounds__(256) void gemm_tf32(
    int xsel, long xoff, const float* __restrict__ W, const float* __restrict__ bias,
    int csel, long coff, int caddsel, long caddoff,
    int M, int N, int K, float* dout)
{
    const float* X = (const float*)buf_ptr(xsel, dout) + xoff;
    float* C = buf_ptr(csel, dout) + coff;
    const float* Cadd = (caddsel >= 0) ? ((const float*)buf_ptr(caddsel, dout) + caddoff) : nullptr;

    __shared__ unsigned Xs[2][128 * GP];
    __shared__ unsigned Ws[2][128 * GP];

    const int tid = threadIdx.x;
    const int lane = tid & 31, w = tid >> 5;
    const int wm = (w & 3) * 32, wn = (w >> 2) * 64;
    const long bm = (long)blockIdx.y * 128, bn = (long)blockIdx.x * 128;

    float acc[2][8][4];
#pragma unroll
    for (int mf = 0; mf < 2; mf++)
#pragma unroll
        for (int nf = 0; nf < 8; nf++)
#pragma unroll
            for (int r = 0; r < 4; r++) acc[mf][nf][r] = 0.f;

    const bool fast = ((K & 15) == 0);
    const int niter = (K + 15) / 16;

    float4 xr[2], wr[2];

    auto LOADG = [&](int it) {
        int k0 = it * 16;
#pragma unroll
        for (int rr = 0; rr < 2; rr++) {
            int slot = tid + rr * 256;
            int row = slot >> 2, kc = (slot & 3) * 4;
            if (fast) {
                xr[rr] = *(const float4*)(X + (bm + row) * (long)K + k0 + kc);
                wr[rr] = *(const float4*)(W + (bn + row) * (long)K + k0 + kc);
            } else {
                float tx[4], tw[4];
#pragma unroll
                for (int e = 0; e < 4; e++) {
                    int kk = k0 + kc + e;
                    tx[e] = (kk < K) ? X[(bm + row) * (long)K + kk] : 0.f;
                    tw[e] = (kk < K) ? W[(bn + row) * (long)K + kk] : 0.f;
                }
                xr[rr] = make_float4(tx[0], tx[1], tx[2], tx[3]);
                wr[rr] = make_float4(tw[0], tw[1], tw[2], tw[3]);
            }
        }
    };
    auto STOREG = [&](int buf) {
#pragma unroll
        for (int rr = 0; rr < 2; rr++) {
            int slot = tid + rr * 256;
            int row = slot >> 2, kc = (slot & 3) * 4;
            unsigned* px = &Xs[buf][row * GP + kc];
            px[0] = f2tf(xr[rr].x); px[1] = f2tf(xr[rr].y);
            px[2] = f2tf(xr[rr].z); px[3] = f2tf(xr[rr].w);
            unsigned* pw = &Ws[buf][row * GP + kc];
            pw[0] = f2tf(wr[rr].x); pw[1] = f2tf(wr[rr].y);
            pw[2] = f2tf(wr[rr].z); pw[3] = f2tf(wr[rr].w);
        }
    };

    LOADG(0);
    STOREG(0);
    if (niter > 1) LOADG(1);
    __syncthreads();

    for (int it = 0; it < niter; it++) {
        const int cur = it & 1;
        if (it + 1 < niter) STOREG(1 - cur);
        if (it + 2 < niter) LOADG(it + 2);
#pragma unroll
        for (int kf = 0; kf < 2; kf++) {
            const int kb = kf * 8 + (lane & 3);
            unsigned a[2][4];
#pragma unroll
            for (int mf = 0; mf < 2; mf++) {
                const int rb = wm + mf * 16 + (lane >> 2);
                a[mf][0] = Xs[cur][rb * GP + kb];
                a[mf][1] = Xs[cur][(rb + 8) * GP + kb];
                a[mf][2] = Xs[cur][rb * GP + kb + 4];
                a[mf][3] = Xs[cur][(rb + 8) * GP + kb + 4];
            }
#pragma unroll
            for (int nf = 0; nf < 8; nf++) {
                const int nr = wn + nf * 8 + (lane >> 2);
                unsigned b0 = Ws[cur][nr * GP + kb];
                unsigned b1 = Ws[cur][nr * GP + kb + 4];
                mma8(acc[0][nf], a[0][0], a[0][1], a[0][2], a[0][3], b0, b1);
                mma8(acc[1][nf], a[1][0], a[1][1], a[1][2], a[1][3], b0, b1);
            }
        }
        __syncthreads();
    }

#pragma unroll
    for (int mf = 0; mf < 2; mf++)
#pragma unroll
        for (int nf = 0; nf < 8; nf++)
#pragma unroll
            for (int h = 0; h < 2; h++) {
                long m = bm + wm + mf * 16 + (lane >> 2) + h * 8;
                long n = bn + wn + nf * 8 + 2 * (lane & 3);
                float v0 = acc[mf][nf][h * 2 + 0] + bias[n];
                float v1 = acc[mf][nf][h * 2 + 1] + bias[n + 1];
                if (Cadd) { v0 += Cadd[m * N + n]; v1 += Cadd[m * N + n + 1]; }
                *(float2*)(C + m * N + n) = make_float2(v0, v1);
            }
}

// ---------------- persistent LSTM pass — pair-local A staging, no block syncs in k-loop ----------------
// Block tile: 256 batch x 16 h-cols x 4 gates. 8 m-warp-pairs; each pair (2 warps sharing
// wm_i) stages its own 32x16 h-tile into a private double buffer and syncs with a 2-warp
// named barrier (bar.sync 1+wm_i, 64). Whh slice resident in smem. Group-local grid barrier.
// modes: 0 pep1 (2 dirs, 128 blocks), 1 gly1 (64), 2 gly2 (64), 3 pep2 (128)
extern __shared__ unsigned p_smem[];
__global__ __launch_bounds__(PTHREADS) void persist_lstm(
    int mode, int nsteps, const float* __restrict__ Whh0, const float* __restrict__ Whh1,
    float* __restrict__ dout)
{
    unsigned* Wsm = p_smem;                    // 64 x WSTRIDE

    const int tid = threadIdx.x;
    const int lane = tid & 31, w = tid >> 5;
    const int wm_i = w & 7;       // 8 m-warp-pairs, 32 batch rows each
    const int wn_i = w >> 3;      // 2 n-warps per pair

    unsigned* Apair = p_smem + WSM_WORDS + wm_i * APAIR_WORDS;
    unsigned* AbufA = Apair;                   // 32 x GP
    unsigned* AbufB = Apair + 32 * GP;

    int r = blockIdx.x, dir = 0;
    if (mode == 0 || mode == 3) { dir = r >> 6; r &= 63; }
    const int bm = (r >> 5) * PBM;       // 0 or 256
    const int bn = (r & 31) * PBN;       // 0..496
    const int grp = dir * 2 + (r >> 5);  // 32 blocks per group, all modes
    const float* __restrict__ Whh = dir ? Whh1 : Whh0;

    // ---- load + convert weight slice into smem (once): 8192 float4 slots / 512 thr ----
#pragma unroll 4
    for (int rr = 0; rr < 16; rr++) {
        int slot = tid + rr * PTHREADS;      // 0..8191
        int row = slot >> 7;                 // 0..63
        int c4 = (slot & 127) * 4;           // 0..508
        int g = row >> 4, j = row & 15;
        const float* src = Whh + ((long)(g * HH + bn + j)) * HH + c4;
        float4 v = *(const float4*)src;
        unsigned* dst = &Wsm[row * WSTRIDE + c4];
        dst[0] = f2tf(v.x); dst[1] = f2tf(v.y); dst[2] = f2tf(v.z); dst[3] = f2tf(v.w);
    }
    __syncthreads();

    // pair-local A staging coordinates (fixed per thread)
    const int arow = wn_i * 16 + (lane >> 1);   // 0..31 across the pair
    const int ak0 = (lane & 1) * 8;             // 0 or 8

    for (int s = 0; s < nsteps; s++) {
        // ---- per-step pointers ----
        const float* xz; long xz_bs;
        const float* hp = nullptr; long hp_bs = 0;
        float* cbuf; float* hout; long ho_bs;
        const bool first = (s == 0);

        if (mode == 0 || mode == 3) {
            int t = dir ? (LL - 1 - s) : s;
            int tp = dir ? (t + 1) : (t - 1);
            xz = g_xz + (long)t * BB * (2 * ZN) + (long)dir * ZN;
            xz_bs = 2 * ZN;
            cbuf = g_c + (long)dir * BB * HH;
            if (mode == 0) {
                hout = g_pep_concat + (long)t * BB * (2 * HH) + dir * HH; ho_bs = 2 * HH;
                if (!first) { hp = g_pep_concat + (long)tp * BB * (2 * HH) + dir * HH; hp_bs = 2 * HH; }
            } else {
                hout = dout + (long)t * (2 * HH) + dir * HH; ho_bs = (long)LL * 2 * HH;
                if (!first) { hp = dout + (long)tp * (2 * HH) + dir * HH; hp_bs = (long)LL * 2 * HH; }
            }
        } else if (mode == 1) {
            int t = GG - 1 - s;
            xz = g_xzg + (long)t * BB * ZN; xz_bs = ZN;
            cbuf = g_cg;
            hout = g_gly1 + (long)t * BB * HH; ho_bs = HH;
            if (!first) { hp = g_gly1 + (long)(t + 1) * BB * HH; hp_bs = HH; }
        } else {
            int t = s;
            xz = g_xzg + (long)t * BB * ZN; xz_bs = ZN;
            cbuf = g_cg;
            float* gbase = dout + (long)LL * BB * 2 * HH;
            hout = gbase + (long)t * HH; ho_bs = (long)GG * HH;
            if (!first) { hp = gbase + (long)(t - 1) * HH; hp_bs = (long)GG * HH; }
        }

        float acc[4][2][4];   // [gate][mfrag][4]
#pragma unroll
        for (int g = 0; g < 4; g++)
#pragma unroll
            for (int mf = 0; mf < 2; mf++)
#pragma unroll
                for (int e = 0; e < 4; e++) acc[g][mf][e] = 0.f;

        if (!first) {
            const float* abase = hp + (long)(bm + wm_i * 32 + arow) * hp_bs + ak0;
            float4 pre0, pre1;
            auto LOADT = [&](int it) {
                const float* p = abase + it * 16;
                pre0 = __ldcg((const float4*)p);
                pre1 = __ldcg((const float4*)(p + 4));
            };
            auto STORET = [&](unsigned* buf) {
                unsigned* q = buf + arow * GP + ak0;
                q[0] = f2tf(pre0.x); q[1] = f2tf(pre0.y);
                q[2] = f2tf(pre0.z); q[3] = f2tf(pre0.w);
                q[4] = f2tf(pre1.x); q[5] = f2tf(pre1.y);
                q[6] = f2tf(pre1.z); q[7] = f2tf(pre1.w);
            };

            LOADT(0); STORET(AbufA);
            LOADT(1);
            asm volatile("bar.sync %0, %1;" :: "r"(1 + wm_i), "r"(64) : "memory");

            for (int it = 0; it < HH / 16; it++) {
                const int cur = it & 1;
                unsigned* curb = cur ? AbufB : AbufA;
                if (it + 1 < HH / 16) STORET(cur ? AbufA : AbufB);
                if (it + 2 < HH / 16) LOADT(it + 2);
#pragma unroll
                for (int kf = 0; kf < 2; kf++) {
                    const int kl = kf * 8 + (lane & 3);
                    const int kg = it * 16 + kl;
                    unsigned a[2][4];
#pragma unroll
                    for (int mf = 0; mf < 2; mf++) {
                        const int rb = mf * 16 + (lane >> 2);   // pair-local row
                        a[mf][0] = curb[rb * GP + kl];
                        a[mf][1] = curb[(rb + 8) * GP + kl];
                        a[mf][2] = curb[rb * GP + kl + 4];
                        a[mf][3] = curb[(rb + 8) * GP + kl + 4];
                    }
#pragma unroll
                    for (int g = 0; g < 4; g++) {
                        const int nr = g * 16 + wn_i * 8 + (lane >> 2);
                        unsigned b0 = Wsm[nr * WSTRIDE + kg];
                        unsigned b1 = Wsm[nr * WSTRIDE + kg + 4];
#pragma unroll
                        for (int mf = 0; mf < 2; mf++)
                            mma8(acc[g][mf], a[mf][0], a[mf][1], a[mf][2], a[mf][3], b0, b1);
                    }
                }
                asm volatile("bar.sync %0, %1;" :: "r"(1 + wm_i), "r"(64) : "memory");
            }
        }

        // ---- epilogue: gates, cell update, h write ----
#pragma unroll
        for (int mf = 0; mf < 2; mf++)
#pragma unroll
            for (int e = 0; e < 4; e++) {
                const int b = bm + wm_i * 32 + mf * 16 + (lane >> 2) + (e >> 1) * 8;
                const int n = bn + wn_i * 8 + 2 * (lane & 3) + (e & 1);
                const float* xzb = xz + (long)b * xz_bs;
                float zi = acc[0][mf][e] + xzb[n];
                float zf = acc[1][mf][e] + xzb[HH + n];
                float zg = acc[2][mf][e] + xzb[2 * HH + n];
                float zo = acc[3][mf][e] + xzb[3 * HH + n];
                float cp = first ? 0.f : cbuf[(long)b * HH + n];
                float ig = 1.f / (1.f + expf(-zi));
                float fg = 1.f / (1.f + expf(-zf));
                float og = 1.f / (1.f + expf(-zo));
                float cn = fg * cp + ig * tanhf(zg);
                float hn = og * tanhf(cn);
                cbuf[(long)b * HH + n] = cn;
                hout[(long)b * ho_bs + n] = hn;
            }

        // ---- group-local barrier (32 blocks sharing (dir, bm)) ----
        __syncthreads();
        if (tid == 0) {
            __threadfence();
            atomicAdd(&g_bars[grp * 32], 1u);
            unsigned target = (unsigned)(s + 1) * 32u;
            volatile unsigned* vb = &g_bars[grp * 32];
            while (*vb < target) __nanosleep(32);
            __threadfence();   // acquire ordering before next step's reads
        }
        __syncthreads();
    }
}

// ---------------- pack / elementwise helpers ----------------
__global__ void pack_pep0_kernel(const float* __restrict__ pep0) {
    int i = blockIdx.x * blockDim.x + threadIdx.x;
    if (i >= LL * BB * PIN) return;
    int k = i % PIN; int m = i / PIN; int t = m / BB, b = m % BB;
    g_pack[i] = pep0[((long)b * LL + t) * PIN + k];
}

__global__ void pack_gly0_kernel(const float* __restrict__ gly0) {
    int i = blockIdx.x * blockDim.x + threadIdx.x;
    if (i >= GG * BB * GIN) return;
    int k = i % GIN; int m = i / GIN; int t = m / BB, b = m % BB;
    g_pack[i] = gly0[((long)b * GG + t) * GIN + k];
}

__global__ void pack_hT_kernel() {
    int i = blockIdx.x * blockDim.x + threadIdx.x;
    if (i >= BB * 2 * HH) return;
    int k = i % (2 * HH); int b = i / (2 * HH);
    int t = (k < HH) ? (LL - 1) : 0;
    g_pack[i] = g_pep_concat[(long)t * BB * (2 * HH) + (long)b * (2 * HH) + k];
}

__global__ void pack_gly2_kernel(const float* __restrict__ gly0) {
    int i = blockIdx.x * blockDim.x + threadIdx.x;
    const int KW = GIN + HH;  // 528
    if (i >= GG * BB * KW) return;
    int k = i % KW; int m = i / KW; int t = m / BB, b = m % BB;
    float v;
    if (k < GIN) v = gly0[((long)b * GG + t) * GIN + k];
    else if (t == 0) v = g_glymod[(long)b * HH + (k - GIN)];
    else v = g_gly1[(long)t * BB * HH + (long)b * HH + (k - GIN)];
    g_pack[i] = v;
}

__global__ void scatter_root_kernel(const int* __restrict__ pos) {
    int b = blockIdx.x;
    int p = pos[b] - 1;
    for (int j = threadIdx.x; j < 2 * HH; j += blockDim.x)
        g_pep_concat[(long)p * BB * (2 * HH) + (long)b * (2 * HH) + j] += g_rootpep[(long)b * (2 * HH) + j];
}

// ---------------- host orchestration ----------------
extern "C" void kernel_launch(void* const* d_in, const int* in_sizes, int n_in,
                              void* d_out, int out_size)
{
    const float* pep0     = (const float*)d_in[0];
    const float* gly0     = (const float*)d_in[1];
    const int*   gpos     = (const int*)d_in[2];
    const float* pep1_Wih = (const float*)d_in[3];
    const float* pep1_Whh = (const float*)d_in[4];
    const float* pep1_b   = (const float*)d_in[5];
    const float* pep2_Wih = (const float*)d_in[6];
    const float* pep2_Whh = (const float*)d_in[7];
    const float* pep2_b   = (const float*)d_in[8];
    const float* gly1_Wih = (const float*)d_in[9];
    const float* gly1_Whh = (const float*)d_in[10];
    const float* gly1_b   = (const float*)d_in[11];
    const float* gly2_Wih = (const float*)d_in[12];
    const float* gly2_Whh = (const float*)d_in[13];
    const float* gly2_b   = (const float*)d_in[14];
    const float* pg_W     = (const float*)d_in[15];
    const float* pg_b     = (const float*)d_in[16];
    const float* gp_W     = (const float*)d_in[17];
    const float* gp_b     = (const float*)d_in[18];
    float* out = (float*)d_out;

    cudaFuncSetAttribute(persist_lstm, cudaFuncAttributeMaxDynamicSharedMemorySize, PERSIST_SMEM);

    auto sg = [&](int xsel, long xoff, const float* W, const float* bias,
                  int csel, long coff, int caddsel, long caddoff,
                  int M, int N, int K) {
        dim3 grid(N / 128, M / 128);
        gemm_tf32<<<grid, 256>>>(xsel, xoff, W, bias, csel, coff, caddsel, caddoff, M, N, K, out);
    };
    auto plstm = [&](int mode, int nsteps, const float* W0, const float* W1, int nblk) {
        reset_bar_kernel<<<1, 128>>>();
        persist_lstm<<<nblk, PTHREADS, PERSIST_SMEM>>>(mode, nsteps, W0, W1, out);
    };

    // 1) pep1 input projection (both dirs merged: W=[4096][26])
    { int n = LL * BB * PIN; pack_pep0_kernel<<<(n + 255) / 256, 256>>>(pep0); }
    sg(0, 0, pep1_Wih, pep1_b, 1, 0, -1, 0, LL * BB, 2 * ZN, PIN);

    // 2) pep BiLSTM 1 (persistent, 48 steps, 2 dirs)
    plstm(0, LL, pep1_Whh, pep1_Whh + (long)ZN * HH, 128);

    // 3) gly TreeLSTM 1 (leaf->root)
    { int n = GG * BB * GIN; pack_gly0_kernel<<<(n + 255) / 256, 256>>>(gly0); }
    sg(0, 0, gly1_Wih, gly1_b, 2, 0, -1, 0, GG * BB, ZN, GIN);
    plstm(1, GG, gly1_Whh, gly1_Whh, 64);

    // 4) glymod = gly_1[:,0,:] + [hTf,hTb] @ pg_W^T + pg_b
    { int n = BB * 2 * HH; pack_hT_kernel<<<(n + 255) / 256, 256>>>(); }
    sg(0, 0, pg_W, pg_b, 5, 0, 4, 0, BB, HH, 2 * HH);

    // 5) root_pep = gly_1[:,0,:] @ gp_W^T + gp_b (unmodified gly_1)
    sg(4, 0, gp_W, gp_b, 6, 0, -1, 0, BB, 2 * HH, HH);

    // 6) scatter root_pep into pep_concat at glycosylation site
    scatter_root_kernel<<<BB, 256>>>(gpos);

    // 7) gly TreeLSTM 2 (root->leaf); writes gly_2 to out
    { int n = GG * BB * (GIN + HH); pack_gly2_kernel<<<(n + 255) / 256, 256>>>(gly0); }
    sg(0, 0, gly2_Wih, gly2_b, 2, 0, -1, 0, GG * BB, ZN, GIN + HH);
    plstm(2, GG, gly2_Whh, gly2_Whh, 64);

    // 8) pep2 input projection (big GEMM: M=24576, N=4096, K=1024)
    sg(3, 0, pep2_Wih, pep2_b, 1, 0, -1, 0, LL * BB, 2 * ZN, 2 * HH);

    // 9) pep BiLSTM 2 (persistent); writes pep_2 directly into out
    plstm(3, LL, pep2_Whh, pep2_Whh + (long)ZN * HH, 128);
}

// round 13
// speedup vs baseline: 1.1195x; 1.1195x over previous
#include <cuda_runtime.h>
#include <math.h>

// Problem dims
#define BB 512
#define LL 48
#define GG 16
#define HH 512
#define ZN 2048   // 4*H
#define PIN 26
#define GIN 16
#define HSW 16    // words per staged-tile row (XOR-swizzled, conflict-free)

// Persistent-kernel tiling: block = 256 batch x 16 h-cols x 4 gates, 512 threads
#define PTHREADS 512
#define PBM 256
#define PBN 16
#define WSTRIDE 516                      // 512 + 4 padding (b-loads conflict-free)
#define WSM_WORDS (64 * WSTRIDE)         // 33024
#define HS_WORDS  (PBM * HSW)            // 4096 per buffer
#define PERSIST_SMEM ((WSM_WORDS + 2 * HS_WORDS) * 4)   // 164,864 bytes

// ---------------- device scratch (static, no allocs) ----------------
__device__ float g_xz[(size_t)LL * BB * 2 * ZN];          // [t][b][dir][2048]
__device__ float g_xzg[(size_t)GG * BB * ZN];             // [t][b][2048]
__device__ float g_pep_concat[(size_t)LL * BB * 2 * HH];  // [t][b][1024]
__device__ float g_gly1[(size_t)GG * BB * HH];            // [t][b][512]
__device__ float g_glymod[(size_t)BB * HH];
__device__ float g_rootpep[(size_t)BB * 2 * HH];
__device__ float g_c[2 * (size_t)BB * HH];
__device__ float g_cg[(size_t)BB * HH];
__device__ float g_pack[(size_t)(GG * BB) * (GIN + HH)];
__device__ unsigned g_bars[4 * 32];   // 4 group counters, 128B apart

__device__ __forceinline__ float* buf_ptr(int sel, float* dout) {
    switch (sel) {
        case 0: return g_pack;
        case 1: return g_xz;
        case 2: return g_xzg;
        case 3: return g_pep_concat;
        case 4: return g_gly1;
        case 5: return g_glymod;
        case 6: return g_rootpep;
        default: return dout;
    }
}

__device__ __forceinline__ unsigned f2tf(float f) {
    unsigned u; asm("cvt.rna.tf32.f32 %0, %1;" : "=r"(u) : "f"(f)); return u;
}

__device__ __forceinline__ void mma8(float* d, unsigned a0, unsigned a1, unsigned a2, unsigned a3,
                                     unsigned b0, unsigned b1) {
    asm volatile(
        "mma.sync.aligned.m16n8k8.row.col.f32.tf32.tf32.f32 "
        "{%0,%1,%2,%3}, {%4,%5,%6,%7}, {%8,%9}, {%0,%1,%2,%3};"
        : "+f"(d[0]), "+f"(d[1]), "+f"(d[2]), "+f"(d[3])
        : "r"(a0), "r"(a1), "r"(a2), "r"(a3), "r"(b0), "r"(b1));
}

__global__ void reset_bar_kernel() {
    if (threadIdx.x < 4 * 32) g_bars[threadIdx.x] = 0;
}

// Swizzled word position within a 16-word tile row: word k of row r at
// r*16 + (k&3) + 4*((k>>2) ^ ((r>>1)&3)).  STS.128 per 4-word chunk is
// conflict-free (each 8-lane phase covers all 32 banks); all LDS fragment
// reads below hit 32 distinct banks.

// ---------------- tf32 tensor-core GEMM (double-buffered, swizzled stages) ----------------
// C[m][n] = bias[n] + (Cadd?) + sum_k X[m*K+k] * W[n*K+k]
// BM=128, BN=128, BK=16, 256 threads (8 warps, 4x2), warp tile 32x64.
__global__ __launch_bounds__(256) void gemm_tf32(
    int xsel, long xoff, const float* __restrict__ W, const float* __restrict__ bias,
    int csel, long coff, int caddsel, long caddoff,
    int M, int N, int K, float* dout)
{
    const float* X = (const float*)buf_ptr(xsel, dout) + xoff;
    float* C = buf_ptr(csel, dout) + coff;
    const float* Cadd = (caddsel >= 0) ? ((const float*)buf_ptr(caddsel, dout) + caddoff) : nullptr;

    __shared__ __align__(16) unsigned Xs[2][128 * HSW];
    __shared__ __align__(16) unsigned Ws[2][128 * HSW];

    const int tid = threadIdx.x;
    const int lane = tid & 31, w = tid >> 5;
    const int wm = (w & 3) * 32, wn = (w >> 2) * 64;
    const long bm = (long)blockIdx.y * 128, bn = (long)blockIdx.x * 128;

    float acc[2][8][4];
#pragma unroll
    for (int mf = 0; mf < 2; mf++)
#pragma unroll
        for (int nf = 0; nf < 8; nf++)
#pragma unroll
            for (int r = 0; r < 4; r++) acc[mf][nf][r] = 0.f;

    const bool fast = ((K & 15) == 0);
    const int niter = (K + 15) / 16;

    float4 xr[2], wr[2];

    auto LOADG = [&](int it) {
        int k0 = it * 16;
#pragma unroll
        for (int rr = 0; rr < 2; rr++) {
            int slot = tid + rr * 256;
            int row = slot >> 2, kc = (slot & 3) * 4;
            if (fast) {
                xr[rr] = *(const float4*)(X + (bm + row) * (long)K + k0 + kc);
                wr[rr] = *(const float4*)(W + (bn + row) * (long)K + k0 + kc);
            } else {
                float tx[4], tw[4];
#pragma unroll
                for (int e = 0; e < 4; e++) {
                    int kk = k0 + kc + e;
                    tx[e] = (kk < K) ? X[(bm + row) * (long)K + kk] : 0.f;
                    tw[e] = (kk < K) ? W[(bn + row) * (long)K + kk] : 0.f;
                }
                xr[rr] = make_float4(tx[0], tx[1], tx[2], tx[3]);
                wr[rr] = make_float4(tw[0], tw[1], tw[2], tw[3]);
            }
        }
    };
    auto STOREG = [&](int buf) {
#pragma unroll
        for (int rr = 0; rr < 2; rr++) {
            int slot = tid + rr * 256;
            int row = slot >> 2, c = slot & 3;
            int pos = row * HSW + ((c ^ ((row >> 1) & 3)) << 2);
            uint4 vx = make_uint4(f2tf(xr[rr].x), f2tf(xr[rr].y), f2tf(xr[rr].z), f2tf(xr[rr].w));
            *(uint4*)&Xs[buf][pos] = vx;
            uint4 vw = make_uint4(f2tf(wr[rr].x), f2tf(wr[rr].y), f2tf(wr[rr].z), f2tf(wr[rr].w));
            *(uint4*)&Ws[buf][pos] = vw;
        }
    };

    LOADG(0);
    STOREG(0);
    if (niter > 1) LOADG(1);
    __syncthreads();

    const int sg = lane & 3;
    for (int it = 0; it < niter; it++) {
        const int cur = it & 1;
        if (it + 1 < niter) STOREG(1 - cur);
        if (it + 2 < niter) LOADG(it + 2);
#pragma unroll
        for (int kf = 0; kf < 2; kf++) {
            unsigned a[2][4];
#pragma unroll
            for (int mf = 0; mf < 2; mf++) {
                const int rb = wm + mf * 16 + (lane >> 2);
                const int s1 = (rb >> 1) & 3;
                const int o0 = ((2 * kf) ^ s1) << 2;       // chunk offset for k
                const int o1 = o0 ^ 4;                     // chunk offset for k+4
                const int base = rb * HSW + sg;
                a[mf][0] = Xs[cur][base + o0];
                a[mf][2] = Xs[cur][base + o1];
                a[mf][1] = Xs[cur][base + 8 * HSW + o0];   // row rb+8 shares s1
                a[mf][3] = Xs[cur][base + 8 * HSW + o1];
            }
#pragma unroll
            for (int nf = 0; nf < 8; nf++) {
                const int nr = wn + nf * 8 + (lane >> 2);
                const int s1n = (nr >> 1) & 3;
                const int p0 = ((2 * kf) ^ s1n) << 2;
                unsigned b0 = Ws[cur][nr * HSW + sg + p0];
                unsigned b1 = Ws[cur][nr * HSW + sg + (p0 ^ 4)];
                mma8(acc[0][nf], a[0][0], a[0][1], a[0][2], a[0][3], b0, b1);
                mma8(acc[1][nf], a[1][0], a[1][1], a[1][2], a[1][3], b0, b1);
            }
        }
        __syncthreads();
    }

#pragma unroll
    for (int mf = 0; mf < 2; mf++)
#pragma unroll
        for (int nf = 0; nf < 8; nf++)
#pragma unroll
            for (int h = 0; h < 2; h++) {
                long m = bm + wm + mf * 16 + (lane >> 2) + h * 8;
                long n = bn + wn + nf * 8 + 2 * (lane & 3);
                float v0 = acc[mf][nf][h * 2 + 0] + bias[n];
                float v1 = acc[mf][nf][h * 2 + 1] + bias[n + 1];
                if (Cadd) { v0 += Cadd[m * N + n]; v1 += Cadd[m * N + n + 1]; }
                *(float2*)(C + m * N + n) = make_float2(v0, v1);
            }
}

// ---------------- persistent LSTM pass — R9 structure + swizzled H staging ----------------
// Block tile: 256 batch x 16 h-cols x 4 gates, 512 threads (8 m-warps x 2 n-warps).
// Whh slice (64 x 512 tf32) resident in smem (WSTRIDE layout, conflict-free loads).
// H tiles staged via STS.128 into XOR-swizzled 16-word rows (conflict-free both ways).
// Group-local grid barrier (32 blocks sharing (dir, bm)); volatile poll.
// modes: 0 pep1 (2 dirs, 128 blocks), 1 gly1 (64), 2 gly2 (64), 3 pep2 (128)
extern __shared__ unsigned p_smem[];
__global__ __launch_bounds__(PTHREADS) void persist_lstm(
    int mode, int nsteps, const float* __restrict__ Whh0, const float* __restrict__ Whh1,
    float* __restrict__ dout)
{
    unsigned* Wsm = p_smem;                    // 64 x WSTRIDE
    unsigned* Hs0 = p_smem + WSM_WORDS;        // 256 x HSW
    unsigned* Hs1 = Hs0 + HS_WORDS;

    const int tid = threadIdx.x;
    const int lane = tid & 31, w = tid >> 5;
    const int wm_i = w & 7;       // 8 m-warps, warp-m = 32 (mf=2 x 16)
    const int wn_i = w >> 3;      // 2 n-warps, warp-n = 8

    int r = blockIdx.x, dir = 0;
    if (mode == 0 || mode == 3) { dir = r >> 6; r &= 63; }
    const int bm = (r >> 5) * PBM;       // 0 or 256
    const int bn = (r & 31) * PBN;       // 0..496
    const int grp = dir * 2 + (r >> 5);  // 32 blocks per group, all modes
    const float* __restrict__ Whh = dir ? Whh1 : Whh0;

    // ---- load + convert weight slice into smem (once): 8192 float4 slots / 512 thr ----
#pragma unroll 4
    for (int rr = 0; rr < 16; rr++) {
        int slot = tid + rr * PTHREADS;      // 0..8191
        int row = slot >> 7;                 // 0..63
        int c4 = (slot & 127) * 4;           // 0..508
        int g = row >> 4, j = row & 15;
        const float* src = Whh + ((long)(g * HH + bn + j)) * HH + c4;
        float4 v = *(const float4*)src;
        unsigned* dst = &Wsm[row * WSTRIDE + c4];
        dst[0] = f2tf(v.x); dst[1] = f2tf(v.y); dst[2] = f2tf(v.z); dst[3] = f2tf(v.w);
    }
    __syncthreads();

    for (int s = 0; s < nsteps; s++) {
        // ---- per-step pointers ----
        const float* xz; long xz_bs;
        const float* hp = nullptr; long hp_bs = 0;
        float* cbuf; float* hout; long ho_bs;
        const bool first = (s == 0);

        if (mode == 0 || mode == 3) {
            int t = dir ? (LL - 1 - s) : s;
            int tp = dir ? (t + 1) : (t - 1);
            xz = g_xz + (long)t * BB * (2 * ZN) + (long)dir * ZN;
            xz_bs = 2 * ZN;
            cbuf = g_c + (long)dir * BB * HH;
            if (mode == 0) {
                hout = g_pep_concat + (long)t * BB * (2 * HH) + dir * HH; ho_bs = 2 * HH;
                if (!first) { hp = g_pep_concat + (long)tp * BB * (2 * HH) + dir * HH; hp_bs = 2 * HH; }
            } else {
                hout = dout + (long)t * (2 * HH) + dir * HH; ho_bs = (long)LL * 2 * HH;
                if (!first) { hp = dout + (long)tp * (2 * HH) + dir * HH; hp_bs = (long)LL * 2 * HH; }
            }
        } else if (mode == 1) {
            int t = GG - 1 - s;
            xz = g_xzg + (long)t * BB * ZN; xz_bs = ZN;
            cbuf = g_cg;
            hout = g_gly1 + (long)t * BB * HH; ho_bs = HH;
            if (!first) { hp = g_gly1 + (long)(t + 1) * BB * HH; hp_bs = HH; }
        } else {
            int t = s;
            xz = g_xzg + (long)t * BB * ZN; xz_bs = ZN;
            cbuf = g_cg;
            float* gbase = dout + (long)LL * BB * 2 * HH;
            hout = gbase + (long)t * HH; ho_bs = (long)GG * HH;
            if (!first) { hp = gbase + (long)(t - 1) * HH; hp_bs = (long)GG * HH; }
        }

        float acc[4][2][4];   // [gate][mfrag][4]
#pragma unroll
        for (int g = 0; g < 4; g++)
#pragma unroll
            for (int mf = 0; mf < 2; mf++)
#pragma unroll
                for (int e = 0; e < 4; e++) acc[g][mf][e] = 0.f;

        if (!first) {
            float4 pre[2];
            auto LOADT = [&](int it) {
                int k0 = it * 16;
#pragma unroll
                for (int rr = 0; rr < 2; rr++) {
                    int slot = tid + rr * PTHREADS;     // 0..1023
                    int row = slot >> 2;                // 0..255
                    int kc = (slot & 3) * 4;
                    pre[rr] = __ldcg((const float4*)(hp + (long)(bm + row) * hp_bs + k0 + kc));
                }
            };
            auto STORET = [&](unsigned* buf) {
#pragma unroll
                for (int rr = 0; rr < 2; rr++) {
                    int slot = tid + rr * PTHREADS;
                    int row = slot >> 2;
                    int c = slot & 3;
                    int pos = row * HSW + ((c ^ ((row >> 1) & 3)) << 2);
                    uint4 v = make_uint4(f2tf(pre[rr].x), f2tf(pre[rr].y),
                                         f2tf(pre[rr].z), f2tf(pre[rr].w));
                    *(uint4*)&buf[pos] = v;
                }
            };

            LOADT(0); STORET(Hs0);
            LOADT(1);
            __syncthreads();

            const int sg = lane & 3;
            for (int it = 0; it < HH / 16; it++) {
                const int cur = it & 1;
                unsigned* curb = cur ? Hs1 : Hs0;
                if (it + 1 < HH / 16) STORET(cur ? Hs0 : Hs1);
                if (it + 2 < HH / 16) LOADT(it + 2);
#pragma unroll
                for (int kf = 0; kf < 2; kf++) {
                    const int kg = it * 16 + kf * 8 + sg;      // global k for b-loads
                    unsigned a[2][4];
#pragma unroll
                    for (int mf = 0; mf < 2; mf++) {
                        const int rb = wm_i * 32 + mf * 16 + (lane >> 2);
                        const int s1 = (rb >> 1) & 3;
                        const int o0 = ((2 * kf) ^ s1) << 2;
                        const int o1 = o0 ^ 4;
                        const int base = rb * HSW + sg;
                        a[mf][0] = curb[base + o0];
                        a[mf][2] = curb[base + o1];
                        a[mf][1] = curb[base + 8 * HSW + o0];  // row rb+8 shares s1
                        a[mf][3] = curb[base + 8 * HSW + o1];
                    }
#pragma unroll
                    for (int g = 0; g < 4; g++) {
                        const int nr = g * 16 + wn_i * 8 + (lane >> 2);
                        unsigned b0 = Wsm[nr * WSTRIDE + kg];
                        unsigned b1 = Wsm[nr * WSTRIDE + kg + 4];
#pragma unroll
                        for (int mf = 0; mf < 2; mf++)
                            mma8(acc[g][mf], a[mf][0], a[mf][1], a[mf][2], a[mf][3], b0, b1);
                    }
                }
                __syncthreads();
            }
        }

        // ---- epilogue: gates, cell update, h write ----
#pragma unroll
        for (int mf = 0; mf < 2; mf++)
#pragma unroll
            for (int e = 0; e < 4; e++) {
                const int b = bm + wm_i * 32 + mf * 16 + (lane >> 2) + (e >> 1) * 8;
                const int n = bn + wn_i * 8 + 2 * (lane & 3) + (e & 1);
                const float* xzb = xz + (long)b * xz_bs;
                float zi = acc[0][mf][e] + xzb[n];
                float zf = acc[1][mf][e] + xzb[HH + n];
                float zg = acc[2][mf][e] + xzb[2 * HH + n];
                float zo = acc[3][mf][e] + xzb[3 * HH + n];
                float cp = first ? 0.f : cbuf[(long)b * HH + n];
                float ig = 1.f / (1.f + expf(-zi));
                float fg = 1.f / (1.f + expf(-zf));
                float og = 1.f / (1.f + expf(-zo));
                float cn = fg * cp + ig * tanhf(zg);
                float hn = og * tanhf(cn);
                cbuf[(long)b * HH + n] = cn;
                hout[(long)b * ho_bs + n] = hn;
            }

        // ---- group-local barrier (32 blocks sharing (dir, bm)) ----
        __syncthreads();
        if (tid == 0) {
            __threadfence();
            atomicAdd(&g_bars[grp * 32], 1u);
            unsigned target = (unsigned)(s + 1) * 32u;
            volatile unsigned* vb = &g_bars[grp * 32];
            while (*vb < target) __nanosleep(32);
            __threadfence();   // acquire ordering before next step's reads
        }
        __syncthreads();
    }
}

// ---------------- pack / elementwise helpers ----------------
__global__ void pack_pep0_kernel(const float* __restrict__ pep0) {
    int i = blockIdx.x * blockDim.x + threadIdx.x;
    if (i >= LL * BB * PIN) return;
    int k = i % PIN; int m = i / PIN; int t = m / BB, b = m % BB;
    g_pack[i] = pep0[((long)b * LL + t) * PIN + k];
}

__global__ void pack_gly0_kernel(const float* __restrict__ gly0) {
    int i = blockIdx.x * blockDim.x + threadIdx.x;
    if (i >= GG * BB * GIN) return;
    int k = i % GIN; int m = i / GIN; int t = m / BB, b = m % BB;
    g_pack[i] = gly0[((long)b * GG + t) * GIN + k];
}

__global__ void pack_hT_kernel() {
    int i = blockIdx.x * blockDim.x + threadIdx.x;
    if (i >= BB * 2 * HH) return;
    int k = i % (2 * HH); int b = i / (2 * HH);
    int t = (k < HH) ? (LL - 1) : 0;
    g_pack[i] = g_pep_concat[(long)t * BB * (2 * HH) + (long)b * (2 * HH) + k];
}

__global__ void pack_gly2_kernel(const float* __restrict__ gly0) {
    int i = blockIdx.x * blockDim.x + threadIdx.x;
    const int KW = GIN + HH;  // 528
    if (i >= GG * BB * KW) return;
    int k = i % KW; int m = i / KW; int t = m / BB, b = m % BB;
    float v;
    if (k < GIN) v = gly0[((long)b * GG + t) * GIN + k];
    else if (t == 0) v = g_glymod[(long)b * HH + (k - GIN)];
    else v = g_gly1[(long)t * BB * HH + (long)b * HH + (k - GIN)];
    g_pack[i] = v;
}

__global__ void scatter_root_kernel(const int* __restrict__ pos) {
    int b = blockIdx.x;
    int p = pos[b] - 1;
    for (int j = threadIdx.x; j < 2 * HH; j += blockDim.x)
        g_pep_concat[(long)p * BB * (2 * HH) + (long)b * (2 * HH) + j] += g_rootpep[(long)b * (2 * HH) + j];
}

// ---------------- host orchestration ----------------
extern "C" void kernel_launch(void* const* d_in, const int* in_sizes, int n_in,
                              void* d_out, int out_size)
{
    const float* pep0     = (const float*)d_in[0];
    const float* gly0     = (const float*)d_in[1];
    const int*   gpos     = (const int*)d_in[2];
    const float* pep1_Wih = (const float*)d_in[3];
    const float* pep1_Whh = (const float*)d_in[4];
    const float* pep1_b   = (const float*)d_in[5];
    const float* pep2_Wih = (const float*)d_in[6];
    const float* pep2_Whh = (const float*)d_in[7];
    const float* pep2_b   = (const float*)d_in[8];
    const float* gly1_Wih = (const float*)d_in[9];
    const float* gly1_Whh = (const float*)d_in[10];
    const float* gly1_b   = (const float*)d_in[11];
    const float* gly2_Wih = (const float*)d_in[12];
    const float* gly2_Whh = (const float*)d_in[13];
    const float* gly2_b   = (const float*)d_in[14];
    const float* pg_W     = (const float*)d_in[15];
    const float* pg_b     = (const float*)d_in[16];
    const float* gp_W     = (const float*)d_in[17];
    const float* gp_b     = (const float*)d_in[18];
    float* out = (float*)d_out;

    cudaFuncSetAttribute(persist_lstm, cudaFuncAttributeMaxDynamicSharedMemorySize, PERSIST_SMEM);

    auto sg = [&](int xsel, long xoff, const float* W, const float* bias,
                  int csel, long coff, int caddsel, long caddoff,
                  int M, int N, int K) {
        dim3 grid(N / 128, M / 128);
        gemm_tf32<<<grid, 256>>>(xsel, xoff, W, bias, csel, coff, caddsel, caddoff, M, N, K, out);
    };
    auto plstm = [&](int mode, int nsteps, const float* W0, const float* W1, int nblk) {
        reset_bar_kernel<<<1, 128>>>();
        persist_lstm<<<nblk, PTHREADS, PERSIST_SMEM>>>(mode, nsteps, W0, W1, out);
    };

    // 1) pep1 input projection (both dirs merged: W=[4096][26])
    { int n = LL * BB * PIN; pack_pep0_kernel<<<(n + 255) / 256, 256>>>(pep0); }
    sg(0, 0, pep1_Wih, pep1_b, 1, 0, -1, 0, LL * BB, 2 * ZN, PIN);

    // 2) pep BiLSTM 1 (persistent, 48 steps, 2 dirs)
    plstm(0, LL, pep1_Whh, pep1_Whh + (long)ZN * HH, 128);

    // 3) gly TreeLSTM 1 (leaf->root)
    { int n = GG * BB * GIN; pack_gly0_kernel<<<(n + 255) / 256, 256>>>(gly0); }
    sg(0, 0, gly1_Wih, gly1_b, 2, 0, -1, 0, GG * BB, ZN, GIN);
    plstm(1, GG, gly1_Whh, gly1_Whh, 64);

    // 4) glymod = gly_1[:,0,:] + [hTf,hTb] @ pg_W^T + pg_b
    { int n = BB * 2 * HH; pack_hT_kernel<<<(n + 255) / 256, 256>>>(); }
    sg(0, 0, pg_W, pg_b, 5, 0, 4, 0, BB, HH, 2 * HH);

    // 5) root_pep = gly_1[:,0,:] @ gp_W^T + gp_b (unmodified gly_1)
    sg(4, 0, gp_W, gp_b, 6, 0, -1, 0, BB, 2 * HH, HH);

    // 6) scatter root_pep into pep_concat at glycosylation site
    scatter_root_kernel<<<BB, 256>>>(gpos);

    // 7) gly TreeLSTM 2 (root->leaf); writes gly_2 to out
    { int n = GG * BB * (GIN + HH); pack_gly2_kernel<<<(n + 255) / 256, 256>>>(gly0); }
    sg(0, 0, gly2_Wih, gly2_b, 2, 0, -1, 0, GG * BB, ZN, GIN + HH);
    plstm(2, GG, gly2_Whh, gly2_Whh, 64);

    // 8) pep2 input projection (big GEMM: M=24576, N=4096, K=1024)
    sg(3, 0, pep2_Wih, pep2_b, 1, 0, -1, 0, LL * BB, 2 * ZN, 2 * HH);

    // 9) pep BiLSTM 2 (persistent); writes pep_2 directly into out
    plstm(3, LL, pep2_Whh, pep2_Whh + (long)ZN * HH, 128);
}